// round 11
// baseline (speedup 1.0000x reference)
#include <cuda_runtime.h>
#include <cuda_fp16.h>
#include <stdint.h>
#include <string.h>
#include <math.h>

// ---------------- problem constants ----------------
#define Bq   4
#define Tt   4096
#define HIDD 1024
#define NHh  16
#define QKd  64
#define VDd  64
#define KSs  4
#define REDd 128
#define Mrows (Bq*Tt)          // 16384
#define CHUNK 128
#define NCH   (Tt/CHUNK)       // 32
#define KCH   32               // K chunks of 32 (K = 1024 for all GEMMs)

// ---------------- device scratch ----------------
__device__ __half g_xh[(size_t)Mrows*HIDD];
__device__ __half g_ah[(size_t)Mrows*HIDD];
__device__ __half g_wqt[HIDD*HIDD];
__device__ __half g_wvt[HIDD*HIDD];
__device__ __half g_wot[HIDD*HIDD];
__device__ __half g_kg1t[REDd*HIDD];
__device__ __half g_v16[(size_t)Mrows*HIDD];    // V in fp16 (scan input)
__device__ float g_h   [(size_t)Mrows*REDd];
__device__ float g_ker [(size_t)Mrows*NHh*KSs];
__device__ float g_u   [(size_t)Mrows*NHh];
__device__ float g_vv  [(size_t)Mrows*NHh];
__device__ float g_A      [Bq*NHh*NCH];
__device__ float g_ctxend [Bq*NHh*NCH*VDd];
__device__ float g_ctxinit[Bq*NHh*NCH*VDd];

// selectors
#define ASEL_X    0
#define ASEL_ATTN 1
#define BSEL_WQ   0
#define BSEL_WV   1
#define BSEL_KG1  2
#define BSEL_WO   3
#define CSEL_V    0
#define CSEL_H    1
#define CSEL_EXT  2
#define CSEL_GATE 3
#define OSEL_WQ   0
#define OSEL_WV   1
#define OSEL_WO   2
#define OSEL_KG1  3

// ---------------- PTX helpers (sm_100-baseline safe) ----------------
__device__ __forceinline__ uint32_t smem_u32(const void* p) {
    uint32_t a;
    asm("{ .reg .u64 t; cvta.to.shared.u64 t, %1; cvt.u32.u64 %0, t; }" : "=r"(a) : "l"(p));
    return a;
}
#define CP16(dst, src) \
    asm volatile("cp.async.cg.shared.global [%0], [%1], 16;" :: "r"(dst), "l"(src))
#define CP_COMMIT() asm volatile("cp.async.commit_group;" ::: "memory")

__device__ __forceinline__ void ldsm4(uint32_t* r, uint32_t addr) {
    asm volatile("ldmatrix.sync.aligned.m8n8.x4.shared.b16 {%0,%1,%2,%3},[%4];"
        : "=r"(r[0]), "=r"(r[1]), "=r"(r[2]), "=r"(r[3]) : "r"(addr));
}
__device__ __forceinline__ void ldsm2(uint32_t* r, uint32_t addr) {
    asm volatile("ldmatrix.sync.aligned.m8n8.x2.shared.b16 {%0,%1},[%2];"
        : "=r"(r[0]), "=r"(r[1]) : "r"(addr));
}
__device__ __forceinline__ void mma16816(float* c, const uint32_t* a, const uint32_t* b) {
    asm volatile("mma.sync.aligned.m16n8k16.row.col.f32.f16.f16.f32 "
        "{%0,%1,%2,%3},{%4,%5,%6,%7},{%8,%9},{%0,%1,%2,%3};"
        : "+f"(c[0]), "+f"(c[1]), "+f"(c[2]), "+f"(c[3])
        : "r"(a[0]), "r"(a[1]), "r"(a[2]), "r"(a[3]), "r"(b[0]), "r"(b[1]));
}

// smem: 4 stages; per stage 2 matrices (A, B), each 128 rows x 80B (32 fp16 + pad)
#define ROW_B     80
#define MAT_BYTES (128*ROW_B)          // 10240
#define STG_BYTES (2*MAT_BYTES)        // 20480
#define SMEM_TOT  (4*STG_BYTES)        // 81920  (gate epilogue reuses 128*132*4 = 67584)

__device__ __forceinline__ void load_stage(
    uint32_t sb, int st, int kc, int rowBase, int colBase,
    const __half* Aa, const __half* Bb, int tid)
{
    const uint32_t base = sb + st * STG_BYTES;
    const char* mats[2] = {
        (const char*)(Aa + (size_t)rowBase * HIDD),
        (const char*)(Bb + (size_t)colBase * HIDD) };
    #pragma unroll
    for (int i = 0; i < 4; i++) {
        const int idx = i * 256 + tid;            // 1024 16B chunks
        const int m   = idx >> 9;
        const int row = (idx >> 2) & 127;
        const int ch  = idx & 3;
        CP16(base + m * MAT_BYTES + row * ROW_B + ch * 16,
             mats[m] + (size_t)row * (HIDD * 2) + kc * 64 + ch * 16);
    }
}

// ---------------- GEMM: C[M,N] = A @ B^T + bias --------------------------------
// B stored [N,K]. act: 0 = bias, 1 = bias + silu, 2 = fused RoPE+gate (no C write)
__global__ __launch_bounds__(256, 1) void gemm_mma(
    int a_sel, int b_sel, int c_sel, float* __restrict__ C_ext,
    const float* __restrict__ bias, int ldC, int act,
    const float* __restrict__ gw, const float* __restrict__ gb)
{
    extern __shared__ char smem[];
    const uint32_t sb = smem_u32(smem);
    const int tid = threadIdx.x, wid = tid >> 5, lane = tid & 31;
    const int wm = wid >> 2, wn = wid & 3;        // 2 x 4 warp grid; warp tile 64 x 32
    const int rowBase = blockIdx.y * 128;
    const int colBase = blockIdx.x * 128;

    const __half *Aa, *Bb;
    Aa = (a_sel == ASEL_X) ? g_xh : g_ah;
    if (b_sel == BSEL_WQ)       Bb = g_wqt;
    else if (b_sel == BSEL_WV)  Bb = g_wvt;
    else if (b_sel == BSEL_KG1) Bb = g_kg1t;
    else                        Bb = g_wot;
    float* C = (c_sel == CSEL_H) ? g_h : C_ext;

    float acc[4][4][4];
    #pragma unroll
    for (int i = 0; i < 4; i++)
        #pragma unroll
        for (int j = 0; j < 4; j++)
            #pragma unroll
            for (int k = 0; k < 4; k++) acc[i][j][k] = 0.f;

    // prologue: 3 stages in flight
    load_stage(sb, 0, 0, rowBase, colBase, Aa, Bb, tid); CP_COMMIT();
    load_stage(sb, 1, 1, rowBase, colBase, Aa, Bb, tid); CP_COMMIT();
    load_stage(sb, 2, 2, rowBase, colBase, Aa, Bb, tid); CP_COMMIT();

    const int g  = lane >> 3;       // ldmatrix x4 group
    const int lr = lane & 7;

    for (int kc = 0; kc < KCH; kc++) {
        asm volatile("cp.async.wait_group 2;" ::: "memory");
        __syncthreads();
        if (kc + 3 < KCH)
            load_stage(sb, (kc + 3) & 3, kc + 3, rowBase, colBase, Aa, Bb, tid);
        CP_COMMIT();   // uniform commit keeps wait_group arithmetic exact

        const uint32_t stb = sb + (kc & 3) * STG_BYTES;
        #pragma unroll
        for (int s = 0; s < 2; s++) {
            uint32_t ah[4][4], bh[4][2];
            #pragma unroll
            for (int i = 0; i < 4; i++) {
                const uint32_t arow = (uint32_t)(wm * 64 + i * 16 + (g & 1) * 8 + lr);
                const uint32_t acol = (uint32_t)(s * 32 + (g >> 1) * 16);
                ldsm4(ah[i], stb + arow * ROW_B + acol);
            }
            #pragma unroll
            for (int j = 0; j < 4; j++) {
                const uint32_t brow = (uint32_t)(wn * 32 + j * 8 + lr);
                const uint32_t bcol = (uint32_t)(s * 32 + (g & 1) * 16);
                ldsm2(bh[j], stb + MAT_BYTES + brow * ROW_B + bcol);
            }
            #pragma unroll
            for (int i = 0; i < 4; i++)
                #pragma unroll
                for (int j = 0; j < 4; j++)
                    mma16816(acc[i][j], ah[i], bh[j]);
        }
    }

    const int q = lane >> 2, r4 = lane & 3;

    if (act == 2) {
        // fused RoPE + gate epilogue: stage fp32 tile (+bias) in smem, then reduce.
        float* sQ = (float*)smem;          // 128 x 132 fp32 = 67.6 KB (reuses stages)
        __syncthreads();                   // all ldsm reads complete before overwrite
        #pragma unroll
        for (int i = 0; i < 4; i++) {
            const int r0 = wm * 64 + i * 16 + q;
            #pragma unroll
            for (int j = 0; j < 4; j++) {
                const int col = wn * 32 + j * 8 + r4 * 2;
                const float b0 = bias[colBase + col], b1 = bias[colBase + col + 1];
                sQ[r0 * 132 + col]           = acc[i][j][0] + b0;
                sQ[r0 * 132 + col + 1]       = acc[i][j][1] + b1;
                sQ[(r0 + 8) * 132 + col]     = acc[i][j][2] + b0;
                sQ[(r0 + 8) * 132 + col + 1] = acc[i][j][3] + b1;
            }
        }
        __syncthreads();
        // warp wid handles rows wid*16 .. wid*16+15, both heads of this tile
        const float freq = powf(10000.0f, -(float)lane / 16.0f);
        const float gw0 = gw[lane * 2],        gw1 = gw[lane * 2 + 1];
        const float gw2 = gw[(lane + 32) * 2], gw3 = gw[(lane + 32) * 2 + 1];
        for (int rr = 0; rr < 16; rr++) {
            const int row  = wid * 16 + rr;
            const int grow = rowBase + row;
            const int t    = grow % Tt;
            float s, c;
            sincosf((float)t * freq, &s, &c);
            #pragma unroll
            for (int hh = 0; hh < 2; hh++) {
                const float q1 = sQ[row * 132 + hh * 64 + lane];
                const float q2 = sQ[row * 132 + hh * 64 + 32 + lane];
                const float r1 = q1 * c - q2 * s;
                const float r2 = q1 * s + q2 * c;
                float du = r1 * gw0 + r2 * gw2;
                float dv = r1 * gw1 + r2 * gw3;
                #pragma unroll
                for (int o = 16; o > 0; o >>= 1) {
                    du += __shfl_down_sync(0xffffffffu, du, o);
                    dv += __shfl_down_sync(0xffffffffu, dv, o);
                }
                if (lane == 0) {
                    const int h = (colBase >> 6) + hh;
                    g_u [(size_t)grow * NHh + h] = 1.f / (1.f + expf(-(du + gb[0])));
                    g_vv[(size_t)grow * NHh + h] = 1.f / (1.f + expf(-(dv + gb[1])));
                }
            }
        }
        return;
    }

    // epilogue: bias (+ optional silu); V goes to fp16, others fp32
    #pragma unroll
    for (int i = 0; i < 4; i++) {
        const int row0 = rowBase + wm * 64 + i * 16 + q;
        #pragma unroll
        for (int j = 0; j < 4; j++) {
            const int col = colBase + wn * 32 + j * 8 + r4 * 2;
            const float b0 = bias[col], b1 = bias[col + 1];
            float v0 = acc[i][j][0] + b0, v1 = acc[i][j][1] + b1;
            float v2 = acc[i][j][2] + b0, v3 = acc[i][j][3] + b1;
            if (act == 1) {
                v0 = v0 / (1.f + expf(-v0));
                v1 = v1 / (1.f + expf(-v1));
                v2 = v2 / (1.f + expf(-v2));
                v3 = v3 / (1.f + expf(-v3));
            }
            if (c_sel == CSEL_V) {
                *(__half2*)(g_v16 + (size_t)row0 * ldC + col)       = __floats2half2_rn(v0, v1);
                *(__half2*)(g_v16 + (size_t)(row0 + 8) * ldC + col) = __floats2half2_rn(v2, v3);
            } else {
                *(float2*)(C + (size_t)row0 * ldC + col)       = make_float2(v0, v1);
                *(float2*)(C + (size_t)(row0 + 8) * ldC + col) = make_float2(v2, v3);
            }
        }
    }
}

// ---------------- x -> fp16 (single plane) ----------------
__global__ void convert_x_kernel(const float* __restrict__ x)
{
    const size_t i = (size_t)blockIdx.x * blockDim.x + threadIdx.x;  // float4 index
    const float4 v = ((const float4*)x)[i];
    __half2 lo = __floats2half2_rn(v.x, v.y);
    __half2 hi = __floats2half2_rn(v.z, v.w);
    uint2 H;
    memcpy(&H.x, &lo, 4);
    memcpy(&H.y, &hi, 4);
    ((uint2*)g_xh)[i] = H;
}

// ---------------- W[K,N] -> Wt [N,K] fp16 ----------------
__global__ void transpose_split_kernel(const float* __restrict__ W, int osel, int N)
{
    __shared__ float tile[32][33];
    const int n0 = blockIdx.x * 32, k0 = blockIdx.y * 32;
    const int tx = threadIdx.x, ty = threadIdx.y;   // 32 x 8
    #pragma unroll
    for (int j = 0; j < 32; j += 8)
        tile[ty + j][tx] = W[(size_t)(k0 + ty + j) * N + n0 + tx];
    __syncthreads();
    __half* dst;
    if (osel == OSEL_WQ)      dst = g_wqt;
    else if (osel == OSEL_WV) dst = g_wvt;
    else if (osel == OSEL_WO) dst = g_wot;
    else                      dst = g_kg1t;
    #pragma unroll
    for (int j = 0; j < 32; j += 8) {
        const int n = n0 + ty + j, k = k0 + tx;
        dst[(size_t)n * HIDD + k] = __float2half_rn(tile[tx][ty + j]);
    }
}

// ---------------- kernels = h @ kg_w2 + kg_b2 (smem-cached w2, 16 rows/block) --
__global__ __launch_bounds__(256) void kernels_kernel(const float* __restrict__ kg_w2,
                                                      const float* __restrict__ kg_b2)
{
    __shared__ float w2s[REDd][64];        // 32 KB
    __shared__ float hs[16][REDd + 4];     // 8.25 KB
    const int tid = threadIdx.x;
    const int row0 = blockIdx.x * 16;
    for (int i = tid; i < REDd * 64; i += 256) w2s[i >> 6][i & 63] = kg_w2[i];
    for (int i = tid; i < 16 * REDd; i += 256) {
        const int r = i >> 7, k = i & 127;
        hs[r][k] = g_h[(size_t)(row0 + r) * REDd + k];
    }
    __syncthreads();
    const int n = tid & 63;
    const int rg = tid >> 6;
    const float bb = kg_b2[n];
    #pragma unroll
    for (int rr = 0; rr < 4; rr++) {
        const int r = rg * 4 + rr;
        float acc = bb;
        #pragma unroll 8
        for (int k = 0; k < REDd; k++) acc += hs[r][k] * w2s[k][n];
        g_ker[(size_t)(row0 + r) * 64 + n] = acc;
    }
}

// ---------------- chunked scan (fused 4-tap Vmix, fp16 V) ----------------
__global__ void scan_pass1()
{
    const int chunk = blockIdx.x, h = blockIdx.y, b = blockIdx.z;
    const int d = threadIdx.x;
    const int bh = b * NHh + h;
    const int t0 = chunk * CHUNK;
    const __half* Vb  = g_v16 + (size_t)(b * Tt) * HIDD + h * VDd + d;
    const float* kerB = g_ker + (size_t)(b * Tt) * NHh * KSs + h * KSs;
    const float* uB   = g_u   + (size_t)(b * Tt) * NHh + h;
    const float* vB   = g_vv  + (size_t)(b * Tt) * NHh + h;
    float v0 = (t0 >= 3) ? __half2float(Vb[(size_t)(t0 - 3) * HIDD]) : 0.f;
    float v1 = (t0 >= 2) ? __half2float(Vb[(size_t)(t0 - 2) * HIDD]) : 0.f;
    float v2 = (t0 >= 1) ? __half2float(Vb[(size_t)(t0 - 1) * HIDD]) : 0.f;
    float ctx = 0.f, Ap = 1.f;
    for (int tt = 0; tt < CHUNK; tt++) {
        const int t = t0 + tt;
        const float  v3 = __half2float(Vb[(size_t)t * HIDD]);
        const float4 kv = *(const float4*)(kerB + (size_t)t * NHh * KSs);
        const float  vm = kv.x * v0 + kv.y * v1 + kv.z * v2 + kv.w * v3;
        const float  uu = uB[(size_t)t * NHh];
        const float  vg = vB[(size_t)t * NHh];
        ctx = ctx * uu + vm * vg;
        Ap *= uu;
        v0 = v1; v1 = v2; v2 = v3;
    }
    g_ctxend[(size_t)(bh * NCH + chunk) * VDd + d] = ctx;
    if (d == 0) g_A[bh * NCH + chunk] = Ap;
}

__global__ void scan_pass2()
{
    const int bh = blockIdx.x, d = threadIdx.x;
    float ctx = 0.f;
    for (int c = 0; c < NCH; c++) {
        g_ctxinit[(size_t)(bh * NCH + c) * VDd + d] = ctx;
        ctx = g_ctxend[(size_t)(bh * NCH + c) * VDd + d] + g_A[bh * NCH + c] * ctx;
    }
}

__global__ void scan_pass3()
{
    const int chunk = blockIdx.x, h = blockIdx.y, b = blockIdx.z;
    const int d = threadIdx.x;
    const int bh = b * NHh + h;
    const int t0 = chunk * CHUNK;
    const __half* Vb  = g_v16 + (size_t)(b * Tt) * HIDD + h * VDd + d;
    const float* kerB = g_ker + (size_t)(b * Tt) * NHh * KSs + h * KSs;
    const float* uB   = g_u   + (size_t)(b * Tt) * NHh + h;
    const float* vB   = g_vv  + (size_t)(b * Tt) * NHh + h;
    const size_t obase = (size_t)(b * Tt) * HIDD + h * VDd + d;
    float v0 = (t0 >= 3) ? __half2float(Vb[(size_t)(t0 - 3) * HIDD]) : 0.f;
    float v1 = (t0 >= 2) ? __half2float(Vb[(size_t)(t0 - 2) * HIDD]) : 0.f;
    float v2 = (t0 >= 1) ? __half2float(Vb[(size_t)(t0 - 1) * HIDD]) : 0.f;
    float ctx = g_ctxinit[(size_t)(bh * NCH + chunk) * VDd + d];
    for (int tt = 0; tt < CHUNK; tt++) {
        const int t = t0 + tt;
        const float  v3 = __half2float(Vb[(size_t)t * HIDD]);
        const float4 kv = *(const float4*)(kerB + (size_t)t * NHh * KSs);
        const float  vm = kv.x * v0 + kv.y * v1 + kv.z * v2 + kv.w * v3;
        const float  uu = uB[(size_t)t * NHh];
        const float  vg = vB[(size_t)t * NHh];
        ctx = ctx * uu + vm * vg;
        g_ah[obase + (size_t)t * HIDD] = __float2half_rn(ctx);
        v0 = v1; v1 = v2; v2 = v3;
    }
}

// ---------------- launch ----------------
extern "C" void kernel_launch(void* const* d_in, const int* in_sizes, int n_in,
                              void* d_out, int out_size)
{
    (void)in_sizes; (void)n_in; (void)out_size;
    const float* x      = (const float*)d_in[0];
    const float* W_q    = (const float*)d_in[1];
    const float* b_q    = (const float*)d_in[2];
    // d_in[3] = W_k, d_in[4] = b_k : dead in the reference
    const float* W_v    = (const float*)d_in[5];
    const float* b_v    = (const float*)d_in[6];
    const float* kg_w1  = (const float*)d_in[7];
    const float* kg_b1  = (const float*)d_in[8];
    const float* kg_w2  = (const float*)d_in[9];
    const float* kg_b2  = (const float*)d_in[10];
    const float* gate_w = (const float*)d_in[11];
    const float* gate_b = (const float*)d_in[12];
    const float* W_out  = (const float*)d_in[13];
    const float* b_out  = (const float*)d_in[14];
    float* out = (float*)d_out;

    cudaFuncSetAttribute(gemm_mma, cudaFuncAttributeMaxDynamicSharedMemorySize, SMEM_TOT);

    // input conversions
    convert_x_kernel<<<(Mrows * HIDD / 4) / 256, 256>>>(x);
    transpose_split_kernel<<<dim3(HIDD / 32, HIDD / 32), dim3(32, 8)>>>(W_q,   OSEL_WQ,  HIDD);
    transpose_split_kernel<<<dim3(HIDD / 32, HIDD / 32), dim3(32, 8)>>>(W_v,   OSEL_WV,  HIDD);
    transpose_split_kernel<<<dim3(HIDD / 32, HIDD / 32), dim3(32, 8)>>>(W_out, OSEL_WO,  HIDD);
    transpose_split_kernel<<<dim3(REDd / 32, HIDD / 32), dim3(32, 8)>>>(kg_w1, OSEL_KG1, REDd);

    // Q GEMM with fused RoPE+gate epilogue (writes g_u / g_vv, Q never materialized)
    gemm_mma<<<dim3(HIDD / 128, Mrows / 128), 256, SMEM_TOT>>>(
        ASEL_X, BSEL_WQ, CSEL_GATE, nullptr, b_q, HIDD, 2, gate_w, gate_b);
    // V = x @ W_v + b_v  (fp16 output)
    gemm_mma<<<dim3(HIDD / 128, Mrows / 128), 256, SMEM_TOT>>>(
        ASEL_X, BSEL_WV, CSEL_V, nullptr, b_v, HIDD, 0, nullptr, nullptr);
    // h = silu(x @ kg_w1 + kg_b1)
    gemm_mma<<<dim3(REDd / 128, Mrows / 128), 256, SMEM_TOT>>>(
        ASEL_X, BSEL_KG1, CSEL_H, nullptr, kg_b1, REDd, 1, nullptr, nullptr);
    // conv kernels
    kernels_kernel<<<Mrows / 16, 256>>>(kg_w2, kg_b2);
    // chunked linear scan (pass3 writes fp16 attn directly)
    scan_pass1<<<dim3(NCH, NHh, Bq), VDd>>>();
    scan_pass2<<<Bq * NHh, VDd>>>();
    scan_pass3<<<dim3(NCH, NHh, Bq), VDd>>>();
    // out = attn @ W_out + b_out
    gemm_mma<<<dim3(HIDD / 128, Mrows / 128), 256, SMEM_TOT>>>(
        ASEL_ATTN, BSEL_WO, CSEL_EXT, out, b_out, HIDD, 0, nullptr, nullptr);
}

// round 13
// speedup vs baseline: 1.0029x; 1.0029x over previous
#include <cuda_runtime.h>
#include <cuda_fp16.h>
#include <stdint.h>
#include <string.h>
#include <math.h>

// ---------------- problem constants ----------------
#define Bq   4
#define Tt   4096
#define HIDD 1024
#define NHh  16
#define QKd  64
#define VDd  64
#define KSs  4
#define REDd 128
#define Mrows (Bq*Tt)          // 16384
#define CHUNK 64
#define NCH   (Tt/CHUNK)       // 64
#define KCH   32               // K chunks of 32 (K = 1024 for all GEMMs)

// ---------------- device scratch ----------------
__device__ __half g_xh[(size_t)Mrows*HIDD];
__device__ __half g_ah[(size_t)Mrows*HIDD];
__device__ __half g_wqt[HIDD*HIDD];
__device__ __half g_wvt[HIDD*HIDD];
__device__ __half g_wot[HIDD*HIDD];
__device__ __half g_kg1t[REDd*HIDD];
__device__ __half g_v16[(size_t)Mrows*HIDD];    // V in fp16 (scan input)
__device__ float g_h   [(size_t)Mrows*REDd];
__device__ float g_ker [(size_t)Mrows*NHh*KSs];
__device__ float g_u   [(size_t)Mrows*NHh];
__device__ float g_vv  [(size_t)Mrows*NHh];
__device__ float g_A      [Bq*NHh*NCH];
__device__ float g_ctxend [Bq*NHh*NCH*VDd];
__device__ float g_ctxinit[Bq*NHh*NCH*VDd];

// selectors
#define ASEL_X    0
#define ASEL_ATTN 1
#define BSEL_WQ   0
#define BSEL_WV   1
#define BSEL_KG1  2
#define BSEL_WO   3
#define CSEL_V    0
#define CSEL_H    1
#define CSEL_EXT  2
#define CSEL_GATE 3
#define OSEL_WQ   0
#define OSEL_WV   1
#define OSEL_WO   2
#define OSEL_KG1  3

// ---------------- PTX helpers (sm_100-baseline safe) ----------------
__device__ __forceinline__ uint32_t smem_u32(const void* p) {
    uint32_t a;
    asm("{ .reg .u64 t; cvta.to.shared.u64 t, %1; cvt.u32.u64 %0, t; }" : "=r"(a) : "l"(p));
    return a;
}
#define CP16(dst, src) \
    asm volatile("cp.async.cg.shared.global [%0], [%1], 16;" :: "r"(dst), "l"(src))
#define CP_COMMIT() asm volatile("cp.async.commit_group;" ::: "memory")

__device__ __forceinline__ void ldsm4(uint32_t* r, uint32_t addr) {
    asm volatile("ldmatrix.sync.aligned.m8n8.x4.shared.b16 {%0,%1,%2,%3},[%4];"
        : "=r"(r[0]), "=r"(r[1]), "=r"(r[2]), "=r"(r[3]) : "r"(addr));
}
__device__ __forceinline__ void ldsm2(uint32_t* r, uint32_t addr) {
    asm volatile("ldmatrix.sync.aligned.m8n8.x2.shared.b16 {%0,%1},[%2];"
        : "=r"(r[0]), "=r"(r[1]) : "r"(addr));
}
__device__ __forceinline__ void mma16816(float* c, const uint32_t* a, const uint32_t* b) {
    asm volatile("mma.sync.aligned.m16n8k16.row.col.f32.f16.f16.f32 "
        "{%0,%1,%2,%3},{%4,%5,%6,%7},{%8,%9},{%0,%1,%2,%3};"
        : "+f"(c[0]), "+f"(c[1]), "+f"(c[2]), "+f"(c[3])
        : "r"(a[0]), "r"(a[1]), "r"(a[2]), "r"(a[3]), "r"(b[0]), "r"(b[1]));
}

// smem: 4 stages; per stage 2 matrices (A, B), each 128 rows x 80B (32 fp16 + pad)
#define ROW_B     80
#define MAT_BYTES (128*ROW_B)          // 10240
#define STG_BYTES (2*MAT_BYTES)        // 20480
#define SMEM_TOT  (4*STG_BYTES)        // 81920  (gate epilogue reuses 128*132*4 = 67584)

__device__ __forceinline__ void load_stage(
    uint32_t sb, int st, int kc, int rowBase, int colBase,
    const __half* Aa, const __half* Bb, int tid)
{
    const uint32_t base = sb + st * STG_BYTES;
    const char* mats[2] = {
        (const char*)(Aa + (size_t)rowBase * HIDD),
        (const char*)(Bb + (size_t)colBase * HIDD) };
    #pragma unroll
    for (int i = 0; i < 4; i++) {
        const int idx = i * 256 + tid;            // 1024 16B chunks
        const int m   = idx >> 9;
        const int row = (idx >> 2) & 127;
        const int ch  = idx & 3;
        CP16(base + m * MAT_BYTES + row * ROW_B + ch * 16,
             mats[m] + (size_t)row * (HIDD * 2) + kc * 64 + ch * 16);
    }
}

// ---------------- GEMM: C[M,N] = A @ B^T + bias --------------------------------
// B stored [N,K]. ACT: 0 = bias, 1 = bias + silu, 2 = fused RoPE+gate (no C write)
// Templated so the gate epilogue cannot inflate register pressure of plain GEMMs.
template<int ACT>
__global__ __launch_bounds__(256, 1) void gemm_mma(
    int a_sel, int b_sel, int c_sel, float* __restrict__ C_ext,
    const float* __restrict__ bias, int ldC,
    const float* __restrict__ gw, const float* __restrict__ gb)
{
    extern __shared__ char smem[];
    const uint32_t sb = smem_u32(smem);
    const int tid = threadIdx.x, wid = tid >> 5, lane = tid & 31;
    const int wm = wid >> 2, wn = wid & 3;        // 2 x 4 warp grid; warp tile 64 x 32
    const int rowBase = blockIdx.y * 128;
    const int colBase = blockIdx.x * 128;

    const __half *Aa, *Bb;
    Aa = (a_sel == ASEL_X) ? g_xh : g_ah;
    if (b_sel == BSEL_WQ)       Bb = g_wqt;
    else if (b_sel == BSEL_WV)  Bb = g_wvt;
    else if (b_sel == BSEL_KG1) Bb = g_kg1t;
    else                        Bb = g_wot;
    float* C = (c_sel == CSEL_H) ? g_h : C_ext;

    float acc[4][4][4];
    #pragma unroll
    for (int i = 0; i < 4; i++)
        #pragma unroll
        for (int j = 0; j < 4; j++)
            #pragma unroll
            for (int k = 0; k < 4; k++) acc[i][j][k] = 0.f;

    // prologue: 3 stages in flight
    load_stage(sb, 0, 0, rowBase, colBase, Aa, Bb, tid); CP_COMMIT();
    load_stage(sb, 1, 1, rowBase, colBase, Aa, Bb, tid); CP_COMMIT();
    load_stage(sb, 2, 2, rowBase, colBase, Aa, Bb, tid); CP_COMMIT();

    const int g  = lane >> 3;       // ldmatrix x4 group
    const int lr = lane & 7;

    for (int kc = 0; kc < KCH; kc++) {
        asm volatile("cp.async.wait_group 2;" ::: "memory");
        __syncthreads();
        if (kc + 3 < KCH)
            load_stage(sb, (kc + 3) & 3, kc + 3, rowBase, colBase, Aa, Bb, tid);
        CP_COMMIT();   // uniform commit keeps wait_group arithmetic exact

        const uint32_t stb = sb + (kc & 3) * STG_BYTES;
        #pragma unroll
        for (int s = 0; s < 2; s++) {
            uint32_t ah[4][4], bh[4][2];
            #pragma unroll
            for (int i = 0; i < 4; i++) {
                const uint32_t arow = (uint32_t)(wm * 64 + i * 16 + (g & 1) * 8 + lr);
                const uint32_t acol = (uint32_t)(s * 32 + (g >> 1) * 16);
                ldsm4(ah[i], stb + arow * ROW_B + acol);
            }
            #pragma unroll
            for (int j = 0; j < 4; j++) {
                const uint32_t brow = (uint32_t)(wn * 32 + j * 8 + lr);
                const uint32_t bcol = (uint32_t)(s * 32 + (g & 1) * 16);
                ldsm2(bh[j], stb + MAT_BYTES + brow * ROW_B + bcol);
            }
            #pragma unroll
            for (int i = 0; i < 4; i++)
                #pragma unroll
                for (int j = 0; j < 4; j++)
                    mma16816(acc[i][j], ah[i], bh[j]);
        }
    }

    const int q = lane >> 2, r4 = lane & 3;

    if (ACT == 2) {
        // fused RoPE + gate epilogue: stage fp32 tile (+bias) in smem, then reduce.
        float* sQ = (float*)smem;          // 128 x 132 fp32 = 67.6 KB (reuses stages)
        __syncthreads();                   // all ldsm reads complete before overwrite
        #pragma unroll
        for (int i = 0; i < 4; i++) {
            const int r0 = wm * 64 + i * 16 + q;
            #pragma unroll
            for (int j = 0; j < 4; j++) {
                const int col = wn * 32 + j * 8 + r4 * 2;
                const float b0 = bias[colBase + col], b1 = bias[colBase + col + 1];
                sQ[r0 * 132 + col]           = acc[i][j][0] + b0;
                sQ[r0 * 132 + col + 1]       = acc[i][j][1] + b1;
                sQ[(r0 + 8) * 132 + col]     = acc[i][j][2] + b0;
                sQ[(r0 + 8) * 132 + col + 1] = acc[i][j][3] + b1;
            }
        }
        __syncthreads();
        // warp wid handles rows wid*16 .. wid*16+15, both heads of this tile
        const float freq = powf(10000.0f, -(float)lane / 16.0f);
        const float gw0 = gw[lane * 2],        gw1 = gw[lane * 2 + 1];
        const float gw2 = gw[(lane + 32) * 2], gw3 = gw[(lane + 32) * 2 + 1];
        for (int rr = 0; rr < 16; rr++) {
            const int row  = wid * 16 + rr;
            const int grow = rowBase + row;
            const int t    = grow % Tt;
            float s, c;
            sincosf((float)t * freq, &s, &c);
            #pragma unroll
            for (int hh = 0; hh < 2; hh++) {
                const float q1 = sQ[row * 132 + hh * 64 + lane];
                const float q2 = sQ[row * 132 + hh * 64 + 32 + lane];
                const float r1 = q1 * c - q2 * s;
                const float r2 = q1 * s + q2 * c;
                float du = r1 * gw0 + r2 * gw2;
                float dv = r1 * gw1 + r2 * gw3;
                #pragma unroll
                for (int o = 16; o > 0; o >>= 1) {
                    du += __shfl_down_sync(0xffffffffu, du, o);
                    dv += __shfl_down_sync(0xffffffffu, dv, o);
                }
                if (lane == 0) {
                    const int h = (colBase >> 6) + hh;
                    g_u [(size_t)grow * NHh + h] = 1.f / (1.f + expf(-(du + gb[0])));
                    g_vv[(size_t)grow * NHh + h] = 1.f / (1.f + expf(-(dv + gb[1])));
                }
            }
        }
        return;
    }

    // epilogue: bias (+ optional silu); V goes to fp16, others fp32
    #pragma unroll
    for (int i = 0; i < 4; i++) {
        const int row0 = rowBase + wm * 64 + i * 16 + q;
        #pragma unroll
        for (int j = 0; j < 4; j++) {
            const int col = colBase + wn * 32 + j * 8 + r4 * 2;
            const float b0 = bias[col], b1 = bias[col + 1];
            float v0 = acc[i][j][0] + b0, v1 = acc[i][j][1] + b1;
            float v2 = acc[i][j][2] + b0, v3 = acc[i][j][3] + b1;
            if (ACT == 1) {
                v0 = v0 / (1.f + expf(-v0));
                v1 = v1 / (1.f + expf(-v1));
                v2 = v2 / (1.f + expf(-v2));
                v3 = v3 / (1.f + expf(-v3));
            }
            if (c_sel == CSEL_V) {
                *(__half2*)(g_v16 + (size_t)row0 * ldC + col)       = __floats2half2_rn(v0, v1);
                *(__half2*)(g_v16 + (size_t)(row0 + 8) * ldC + col) = __floats2half2_rn(v2, v3);
            } else {
                *(float2*)(C + (size_t)row0 * ldC + col)       = make_float2(v0, v1);
                *(float2*)(C + (size_t)(row0 + 8) * ldC + col) = make_float2(v2, v3);
            }
        }
    }
}

// ---------------- x -> fp16 (single plane) ----------------
__global__ void convert_x_kernel(const float* __restrict__ x)
{
    const size_t i = (size_t)blockIdx.x * blockDim.x + threadIdx.x;  // float4 index
    const float4 v = ((const float4*)x)[i];
    __half2 lo = __floats2half2_rn(v.x, v.y);
    __half2 hi = __floats2half2_rn(v.z, v.w);
    uint2 H;
    memcpy(&H.x, &lo, 4);
    memcpy(&H.y, &hi, 4);
    ((uint2*)g_xh)[i] = H;
}

// ---------------- W[K,N] -> Wt [N,K] fp16 ----------------
__global__ void transpose_split_kernel(const float* __restrict__ W, int osel, int N)
{
    __shared__ float tile[32][33];
    const int n0 = blockIdx.x * 32, k0 = blockIdx.y * 32;
    const int tx = threadIdx.x, ty = threadIdx.y;   // 32 x 8
    #pragma unroll
    for (int j = 0; j < 32; j += 8)
        tile[ty + j][tx] = W[(size_t)(k0 + ty + j) * N + n0 + tx];
    __syncthreads();
    __half* dst;
    if (osel == OSEL_WQ)      dst = g_wqt;
    else if (osel == OSEL_WV) dst = g_wvt;
    else if (osel == OSEL_WO) dst = g_wot;
    else                      dst = g_kg1t;
    #pragma unroll
    for (int j = 0; j < 32; j += 8) {
        const int n = n0 + ty + j, k = k0 + tx;
        dst[(size_t)n * HIDD + k] = __float2half_rn(tile[tx][ty + j]);
    }
}

// ---------------- kernels = h @ kg_w2 + kg_b2 (smem-cached w2, 16 rows/block) --
__global__ __launch_bounds__(256) void kernels_kernel(const float* __restrict__ kg_w2,
                                                      const float* __restrict__ kg_b2)
{
    __shared__ float w2s[REDd][64];        // 32 KB
    __shared__ float hs[16][REDd + 4];     // 8.25 KB
    const int tid = threadIdx.x;
    const int row0 = blockIdx.x * 16;
    for (int i = tid; i < REDd * 64; i += 256) w2s[i >> 6][i & 63] = kg_w2[i];
    for (int i = tid; i < 16 * REDd; i += 256) {
        const int r = i >> 7, k = i & 127;
        hs[r][k] = g_h[(size_t)(row0 + r) * REDd + k];
    }
    __syncthreads();
    const int n = tid & 63;
    const int rg = tid >> 6;
    const float bb = kg_b2[n];
    #pragma unroll
    for (int rr = 0; rr < 4; rr++) {
        const int r = rg * 4 + rr;
        float acc = bb;
        #pragma unroll 8
        for (int k = 0; k < REDd; k++) acc += hs[r][k] * w2s[k][n];
        g_ker[(size_t)(row0 + r) * 64 + n] = acc;
    }
}

// ---------------- chunked scan (fused 4-tap Vmix, fp16 V, CHUNK=64) ------------
__global__ void scan_pass1()
{
    const int chunk = blockIdx.x, h = blockIdx.y, b = blockIdx.z;
    const int d = threadIdx.x;
    const int bh = b * NHh + h;
    const int t0 = chunk * CHUNK;
    const __half* Vb  = g_v16 + (size_t)(b * Tt) * HIDD + h * VDd + d;
    const float* kerB = g_ker + (size_t)(b * Tt) * NHh * KSs + h * KSs;
    const float* uB   = g_u   + (size_t)(b * Tt) * NHh + h;
    const float* vB   = g_vv  + (size_t)(b * Tt) * NHh + h;
    float v0 = (t0 >= 3) ? __half2float(Vb[(size_t)(t0 - 3) * HIDD]) : 0.f;
    float v1 = (t0 >= 2) ? __half2float(Vb[(size_t)(t0 - 2) * HIDD]) : 0.f;
    float v2 = (t0 >= 1) ? __half2float(Vb[(size_t)(t0 - 1) * HIDD]) : 0.f;
    float ctx = 0.f, Ap = 1.f;
    for (int tt = 0; tt < CHUNK; tt++) {
        const int t = t0 + tt;
        const float  v3 = __half2float(Vb[(size_t)t * HIDD]);
        const float4 kv = *(const float4*)(kerB + (size_t)t * NHh * KSs);
        const float  vm = kv.x * v0 + kv.y * v1 + kv.z * v2 + kv.w * v3;
        const float  uu = uB[(size_t)t * NHh];
        const float  vg = vB[(size_t)t * NHh];
        ctx = ctx * uu + vm * vg;
        Ap *= uu;
        v0 = v1; v1 = v2; v2 = v3;
    }
    g_ctxend[(size_t)(bh * NCH + chunk) * VDd + d] = ctx;
    if (d == 0) g_A[bh * NCH + chunk] = Ap;
}

__global__ void scan_pass2()
{
    const int bh = blockIdx.x, d = threadIdx.x;
    float ctx = 0.f;
    for (int c = 0; c < NCH; c++) {
        g_ctxinit[(size_t)(bh * NCH + c) * VDd + d] = ctx;
        ctx = g_ctxend[(size_t)(bh * NCH + c) * VDd + d] + g_A[bh * NCH + c] * ctx;
    }
}

__global__ void scan_pass3()
{
    const int chunk = blockIdx.x, h = blockIdx.y, b = blockIdx.z;
    const int d = threadIdx.x;
    const int bh = b * NHh + h;
    const int t0 = chunk * CHUNK;
    const __half* Vb  = g_v16 + (size_t)(b * Tt) * HIDD + h * VDd + d;
    const float* kerB = g_ker + (size_t)(b * Tt) * NHh * KSs + h * KSs;
    const float* uB   = g_u   + (size_t)(b * Tt) * NHh + h;
    const float* vB   = g_vv  + (size_t)(b * Tt) * NHh + h;
    const size_t obase = (size_t)(b * Tt) * HIDD + h * VDd + d;
    float v0 = (t0 >= 3) ? __half2float(Vb[(size_t)(t0 - 3) * HIDD]) : 0.f;
    float v1 = (t0 >= 2) ? __half2float(Vb[(size_t)(t0 - 2) * HIDD]) : 0.f;
    float v2 = (t0 >= 1) ? __half2float(Vb[(size_t)(t0 - 1) * HIDD]) : 0.f;
    float ctx = g_ctxinit[(size_t)(bh * NCH + chunk) * VDd + d];
    for (int tt = 0; tt < CHUNK; tt++) {
        const int t = t0 + tt;
        const float  v3 = __half2float(Vb[(size_t)t * HIDD]);
        const float4 kv = *(const float4*)(kerB + (size_t)t * NHh * KSs);
        const float  vm = kv.x * v0 + kv.y * v1 + kv.z * v2 + kv.w * v3;
        const float  uu = uB[(size_t)t * NHh];
        const float  vg = vB[(size_t)t * NHh];
        ctx = ctx * uu + vm * vg;
        g_ah[obase + (size_t)t * HIDD] = __float2half_rn(ctx);
        v0 = v1; v1 = v2; v2 = v3;
    }
}

// ---------------- launch ----------------
extern "C" void kernel_launch(void* const* d_in, const int* in_sizes, int n_in,
                              void* d_out, int out_size)
{
    (void)in_sizes; (void)n_in; (void)out_size;
    const float* x      = (const float*)d_in[0];
    const float* W_q    = (const float*)d_in[1];
    const float* b_q    = (const float*)d_in[2];
    // d_in[3] = W_k, d_in[4] = b_k : dead in the reference
    const float* W_v    = (const float*)d_in[5];
    const float* b_v    = (const float*)d_in[6];
    const float* kg_w1  = (const float*)d_in[7];
    const float* kg_b1  = (const float*)d_in[8];
    const float* kg_w2  = (const float*)d_in[9];
    const float* kg_b2  = (const float*)d_in[10];
    const float* gate_w = (const float*)d_in[11];
    const float* gate_b = (const float*)d_in[12];
    const float* W_out  = (const float*)d_in[13];
    const float* b_out  = (const float*)d_in[14];
    float* out = (float*)d_out;

    cudaFuncSetAttribute(gemm_mma<0>, cudaFuncAttributeMaxDynamicSharedMemorySize, SMEM_TOT);
    cudaFuncSetAttribute(gemm_mma<1>, cudaFuncAttributeMaxDynamicSharedMemorySize, SMEM_TOT);
    cudaFuncSetAttribute(gemm_mma<2>, cudaFuncAttributeMaxDynamicSharedMemorySize, SMEM_TOT);

    // input conversions
    convert_x_kernel<<<(Mrows * HIDD / 4) / 256, 256>>>(x);
    transpose_split_kernel<<<dim3(HIDD / 32, HIDD / 32), dim3(32, 8)>>>(W_q,   OSEL_WQ,  HIDD);
    transpose_split_kernel<<<dim3(HIDD / 32, HIDD / 32), dim3(32, 8)>>>(W_v,   OSEL_WV,  HIDD);
    transpose_split_kernel<<<dim3(HIDD / 32, HIDD / 32), dim3(32, 8)>>>(W_out, OSEL_WO,  HIDD);
    transpose_split_kernel<<<dim3(REDd / 32, HIDD / 32), dim3(32, 8)>>>(kg_w1, OSEL_KG1, REDd);

    // Q GEMM with fused RoPE+gate epilogue (writes g_u / g_vv, Q never materialized)
    gemm_mma<2><<<dim3(HIDD / 128, Mrows / 128), 256, SMEM_TOT>>>(
        ASEL_X, BSEL_WQ, CSEL_GATE, nullptr, b_q, HIDD, gate_w, gate_b);
    // V = x @ W_v + b_v  (fp16 output)
    gemm_mma<0><<<dim3(HIDD / 128, Mrows / 128), 256, SMEM_TOT>>>(
        ASEL_X, BSEL_WV, CSEL_V, nullptr, b_v, HIDD, nullptr, nullptr);
    // h = silu(x @ kg_w1 + kg_b1)
    gemm_mma<1><<<dim3(REDd / 128, Mrows / 128), 256, SMEM_TOT>>>(
        ASEL_X, BSEL_KG1, CSEL_H, nullptr, kg_b1, REDd, nullptr, nullptr);
    // conv kernels
    kernels_kernel<<<Mrows / 16, 256>>>(kg_w2, kg_b2);
    // chunked linear scan (pass3 writes fp16 attn directly)
    scan_pass1<<<dim3(NCH, NHh, Bq), VDd>>>();
    scan_pass2<<<Bq * NHh, VDd>>>();
    scan_pass3<<<dim3(NCH, NHh, Bq), VDd>>>();
    // out = attn @ W_out + b_out
    gemm_mma<0><<<dim3(HIDD / 128, Mrows / 128), 256, SMEM_TOT>>>(
        ASEL_ATTN, BSEL_WO, CSEL_EXT, out, b_out, HIDD, nullptr, nullptr);
}

// round 14
// speedup vs baseline: 1.0612x; 1.0581x over previous
#include <cuda_runtime.h>
#include <cuda_fp16.h>
#include <stdint.h>
#include <string.h>
#include <math.h>

// ---------------- problem constants ----------------
#define Bq   4
#define Tt   4096
#define HIDD 1024
#define NHh  16
#define QKd  64
#define VDd  64
#define KSs  4
#define REDd 128
#define Mrows (Bq*Tt)          // 16384
#define CHUNK 64
#define NCH   (Tt/CHUNK)       // 64
#define KCH   32               // K chunks of 32 (K = 1024 for all GEMMs)

// ---------------- device scratch ----------------
__device__ __half g_xh[(size_t)Mrows*HIDD];
__device__ __half g_ah[(size_t)Mrows*HIDD];
__device__ __half g_wqt[HIDD*HIDD];
__device__ __half g_wvt[HIDD*HIDD];
__device__ __half g_wot[HIDD*HIDD];
__device__ __half g_kg1t[REDd*HIDD];
__device__ __half g_v16[(size_t)Mrows*HIDD];    // V in fp16 (scan input)
__device__ float g_Qf  [(size_t)Mrows*HIDD];    // Q fp32 (gate input)
__device__ float g_h   [(size_t)Mrows*REDd];
__device__ float g_ker [(size_t)Mrows*NHh*KSs];
__device__ float g_u   [(size_t)Mrows*NHh];
__device__ float g_vv  [(size_t)Mrows*NHh];
__device__ float g_A      [Bq*NHh*NCH];
__device__ float g_ctxend [Bq*NHh*NCH*VDd];
__device__ float g_ctxinit[Bq*NHh*NCH*VDd];

// selectors
#define ASEL_X    0
#define ASEL_ATTN 1
#define BSEL_WQ   0
#define BSEL_WV   1
#define BSEL_KG1  2
#define BSEL_WO   3
#define CSEL_V    0
#define CSEL_H    1
#define CSEL_Q    2
#define CSEL_EXT  3
#define OSEL_WQ   0
#define OSEL_WV   1
#define OSEL_WO   2
#define OSEL_KG1  3

// ---------------- PTX helpers (sm_100-baseline safe) ----------------
__device__ __forceinline__ uint32_t smem_u32(const void* p) {
    uint32_t a;
    asm("{ .reg .u64 t; cvta.to.shared.u64 t, %1; cvt.u32.u64 %0, t; }" : "=r"(a) : "l"(p));
    return a;
}
#define CP16(dst, src) \
    asm volatile("cp.async.cg.shared.global [%0], [%1], 16;" :: "r"(dst), "l"(src))
#define CP_COMMIT() asm volatile("cp.async.commit_group;" ::: "memory")

__device__ __forceinline__ void ldsm4(uint32_t* r, uint32_t addr) {
    asm volatile("ldmatrix.sync.aligned.m8n8.x4.shared.b16 {%0,%1,%2,%3},[%4];"
        : "=r"(r[0]), "=r"(r[1]), "=r"(r[2]), "=r"(r[3]) : "r"(addr));
}
__device__ __forceinline__ void ldsm2(uint32_t* r, uint32_t addr) {
    asm volatile("ldmatrix.sync.aligned.m8n8.x2.shared.b16 {%0,%1},[%2];"
        : "=r"(r[0]), "=r"(r[1]) : "r"(addr));
}
__device__ __forceinline__ void mma16816(float* c, const uint32_t* a, const uint32_t* b) {
    asm volatile("mma.sync.aligned.m16n8k16.row.col.f32.f16.f16.f32 "
        "{%0,%1,%2,%3},{%4,%5,%6,%7},{%8,%9},{%0,%1,%2,%3};"
        : "+f"(c[0]), "+f"(c[1]), "+f"(c[2]), "+f"(c[3])
        : "r"(a[0]), "r"(a[1]), "r"(a[2]), "r"(a[3]), "r"(b[0]), "r"(b[1]));
}

// smem: 4 stages; per stage 2 matrices (A, B), each 128 rows x 80B (32 fp16 + pad)
#define ROW_B     80
#define MAT_BYTES (128*ROW_B)          // 10240
#define STG_BYTES (2*MAT_BYTES)        // 20480
#define SMEM_TOT  (4*STG_BYTES)        // 81920

__device__ __forceinline__ void load_stage(
    uint32_t sb, int st, int kc, int rowBase, int colBase,
    const __half* Aa, const __half* Bb, int tid)
{
    const uint32_t base = sb + st * STG_BYTES;
    const char* mats[2] = {
        (const char*)(Aa + (size_t)rowBase * HIDD),
        (const char*)(Bb + (size_t)colBase * HIDD) };
    #pragma unroll
    for (int i = 0; i < 4; i++) {
        const int idx = i * 256 + tid;            // 1024 16B chunks
        const int m   = idx >> 9;
        const int row = (idx >> 2) & 127;
        const int ch  = idx & 3;
        CP16(base + m * MAT_BYTES + row * ROW_B + ch * 16,
             mats[m] + (size_t)row * (HIDD * 2) + kc * 64 + ch * 16);
    }
}

// ---------------- GEMM: C[M,N] = A @ B^T + bias --------------------------------
// B stored [N,K]. ACT: 0 = bias, 1 = bias + silu
template<int ACT>
__global__ __launch_bounds__(256, 1) void gemm_mma(
    int a_sel, int b_sel, int c_sel, float* __restrict__ C_ext,
    const float* __restrict__ bias, int ldC)
{
    extern __shared__ char smem[];
    const uint32_t sb = smem_u32(smem);
    const int tid = threadIdx.x, wid = tid >> 5, lane = tid & 31;
    const int wm = wid >> 2, wn = wid & 3;        // 2 x 4 warp grid; warp tile 64 x 32
    const int rowBase = blockIdx.y * 128;
    const int colBase = blockIdx.x * 128;

    const __half *Aa, *Bb;
    Aa = (a_sel == ASEL_X) ? g_xh : g_ah;
    if (b_sel == BSEL_WQ)       Bb = g_wqt;
    else if (b_sel == BSEL_WV)  Bb = g_wvt;
    else if (b_sel == BSEL_KG1) Bb = g_kg1t;
    else                        Bb = g_wot;
    float* C = (c_sel == CSEL_H) ? g_h : (c_sel == CSEL_Q) ? g_Qf : C_ext;

    float acc[4][4][4];
    #pragma unroll
    for (int i = 0; i < 4; i++)
        #pragma unroll
        for (int j = 0; j < 4; j++)
            #pragma unroll
            for (int k = 0; k < 4; k++) acc[i][j][k] = 0.f;

    // prologue: 3 stages in flight
    load_stage(sb, 0, 0, rowBase, colBase, Aa, Bb, tid); CP_COMMIT();
    load_stage(sb, 1, 1, rowBase, colBase, Aa, Bb, tid); CP_COMMIT();
    load_stage(sb, 2, 2, rowBase, colBase, Aa, Bb, tid); CP_COMMIT();

    const int g  = lane >> 3;       // ldmatrix x4 group
    const int lr = lane & 7;

    for (int kc = 0; kc < KCH; kc++) {
        asm volatile("cp.async.wait_group 2;" ::: "memory");
        __syncthreads();
        if (kc + 3 < KCH)
            load_stage(sb, (kc + 3) & 3, kc + 3, rowBase, colBase, Aa, Bb, tid);
        CP_COMMIT();   // uniform commit keeps wait_group arithmetic exact

        const uint32_t stb = sb + (kc & 3) * STG_BYTES;
        #pragma unroll
        for (int s = 0; s < 2; s++) {
            uint32_t ah[4][4], bh[4][2];
            #pragma unroll
            for (int i = 0; i < 4; i++) {
                const uint32_t arow = (uint32_t)(wm * 64 + i * 16 + (g & 1) * 8 + lr);
                const uint32_t acol = (uint32_t)(s * 32 + (g >> 1) * 16);
                ldsm4(ah[i], stb + arow * ROW_B + acol);
            }
            #pragma unroll
            for (int j = 0; j < 4; j++) {
                const uint32_t brow = (uint32_t)(wn * 32 + j * 8 + lr);
                const uint32_t bcol = (uint32_t)(s * 32 + (g & 1) * 16);
                ldsm2(bh[j], stb + MAT_BYTES + brow * ROW_B + bcol);
            }
            #pragma unroll
            for (int i = 0; i < 4; i++)
                #pragma unroll
                for (int j = 0; j < 4; j++)
                    mma16816(acc[i][j], ah[i], bh[j]);
        }
    }

    // epilogue: bias (+ optional silu); V goes to fp16, others fp32
    const int q = lane >> 2, r4 = lane & 3;
    #pragma unroll
    for (int i = 0; i < 4; i++) {
        const int row0 = rowBase + wm * 64 + i * 16 + q;
        #pragma unroll
        for (int j = 0; j < 4; j++) {
            const int col = colBase + wn * 32 + j * 8 + r4 * 2;
            const float b0 = bias[col], b1 = bias[col + 1];
            float v0 = acc[i][j][0] + b0, v1 = acc[i][j][1] + b1;
            float v2 = acc[i][j][2] + b0, v3 = acc[i][j][3] + b1;
            if (ACT == 1) {
                v0 = v0 / (1.f + expf(-v0));
                v1 = v1 / (1.f + expf(-v1));
                v2 = v2 / (1.f + expf(-v2));
                v3 = v3 / (1.f + expf(-v3));
            }
            if (c_sel == CSEL_V) {
                *(__half2*)(g_v16 + (size_t)row0 * ldC + col)       = __floats2half2_rn(v0, v1);
                *(__half2*)(g_v16 + (size_t)(row0 + 8) * ldC + col) = __floats2half2_rn(v2, v3);
            } else {
                *(float2*)(C + (size_t)row0 * ldC + col)       = make_float2(v0, v1);
                *(float2*)(C + (size_t)(row0 + 8) * ldC + col) = make_float2(v2, v3);
            }
        }
    }
}

// ---------------- x -> fp16 (single plane) ----------------
__global__ void convert_x_kernel(const float* __restrict__ x)
{
    const size_t i = (size_t)blockIdx.x * blockDim.x + threadIdx.x;  // float4 index
    const float4 v = ((const float4*)x)[i];
    __half2 lo = __floats2half2_rn(v.x, v.y);
    __half2 hi = __floats2half2_rn(v.z, v.w);
    uint2 H;
    memcpy(&H.x, &lo, 4);
    memcpy(&H.y, &hi, 4);
    ((uint2*)g_xh)[i] = H;
}

// ---------------- W[K,N] -> Wt [N,K] fp16 ----------------
__global__ void transpose_split_kernel(const float* __restrict__ W, int osel, int N)
{
    __shared__ float tile[32][33];
    const int n0 = blockIdx.x * 32, k0 = blockIdx.y * 32;
    const int tx = threadIdx.x, ty = threadIdx.y;   // 32 x 8
    #pragma unroll
    for (int j = 0; j < 32; j += 8)
        tile[ty + j][tx] = W[(size_t)(k0 + ty + j) * N + n0 + tx];
    __syncthreads();
    __half* dst;
    if (osel == OSEL_WQ)      dst = g_wqt;
    else if (osel == OSEL_WV) dst = g_wvt;
    else if (osel == OSEL_WO) dst = g_wot;
    else                      dst = g_kg1t;
    #pragma unroll
    for (int j = 0; j < 32; j += 8) {
        const int n = n0 + ty + j, k = k0 + tx;
        dst[(size_t)n * HIDD + k] = __float2half_rn(tile[tx][ty + j]);
    }
}

// ---------------- fused RoPE + gate (reads g_Qf) ----------
__global__ void gate_kernel(const float* __restrict__ gate_w,
                            const float* __restrict__ gate_b)
{
    const int gw   = (blockIdx.x * blockDim.x + threadIdx.x) >> 5;
    const int lane = threadIdx.x & 31;
    const int h    = gw % NHh;
    const int bt   = gw / NHh;
    const int t    = bt % Tt;

    const float* qp = g_Qf + (size_t)bt * HIDD + h * QKd;
    const float q1 = qp[lane];
    const float q2 = qp[lane + 32];

    const float freq = powf(10000.0f, -(float)lane / 16.0f);
    float s, c;
    sincosf((float)t * freq, &s, &c);
    const float r1 = q1 * c - q2 * s;
    const float r2 = q1 * s + q2 * c;

    float du = r1 * gate_w[lane * 2]     + r2 * gate_w[(lane + 32) * 2];
    float dv = r1 * gate_w[lane * 2 + 1] + r2 * gate_w[(lane + 32) * 2 + 1];
    #pragma unroll
    for (int o = 16; o > 0; o >>= 1) {
        du += __shfl_down_sync(0xffffffffu, du, o);
        dv += __shfl_down_sync(0xffffffffu, dv, o);
    }
    if (lane == 0) {
        g_u [gw] = 1.f / (1.f + expf(-(du + gate_b[0])));
        g_vv[gw] = 1.f / (1.f + expf(-(dv + gate_b[1])));
    }
}

// ---------------- kernels = h @ kg_w2 + kg_b2 (smem-cached w2, 16 rows/block) --
__global__ __launch_bounds__(256) void kernels_kernel(const float* __restrict__ kg_w2,
                                                      const float* __restrict__ kg_b2)
{
    __shared__ float w2s[REDd][64];        // 32 KB
    __shared__ float hs[16][REDd + 4];     // 8.25 KB
    const int tid = threadIdx.x;
    const int row0 = blockIdx.x * 16;
    for (int i = tid; i < REDd * 64; i += 256) w2s[i >> 6][i & 63] = kg_w2[i];
    for (int i = tid; i < 16 * REDd; i += 256) {
        const int r = i >> 7, k = i & 127;
        hs[r][k] = g_h[(size_t)(row0 + r) * REDd + k];
    }
    __syncthreads();
    const int n = tid & 63;
    const int rg = tid >> 6;
    const float bb = kg_b2[n];
    #pragma unroll
    for (int rr = 0; rr < 4; rr++) {
        const int r = rg * 4 + rr;
        float acc = bb;
        #pragma unroll 8
        for (int k = 0; k < REDd; k++) acc += hs[r][k] * w2s[k][n];
        g_ker[(size_t)(row0 + r) * 64 + n] = acc;
    }
}

// ---------------- chunked scan (fused 4-tap Vmix, fp16 V, CHUNK=64) ------------
__global__ void scan_pass1()
{
    const int chunk = blockIdx.x, h = blockIdx.y, b = blockIdx.z;
    const int d = threadIdx.x;
    const int bh = b * NHh + h;
    const int t0 = chunk * CHUNK;
    const __half* Vb  = g_v16 + (size_t)(b * Tt) * HIDD + h * VDd + d;
    const float* kerB = g_ker + (size_t)(b * Tt) * NHh * KSs + h * KSs;
    const float* uB   = g_u   + (size_t)(b * Tt) * NHh + h;
    const float* vB   = g_vv  + (size_t)(b * Tt) * NHh + h;
    float v0 = (t0 >= 3) ? __half2float(Vb[(size_t)(t0 - 3) * HIDD]) : 0.f;
    float v1 = (t0 >= 2) ? __half2float(Vb[(size_t)(t0 - 2) * HIDD]) : 0.f;
    float v2 = (t0 >= 1) ? __half2float(Vb[(size_t)(t0 - 1) * HIDD]) : 0.f;
    float ctx = 0.f, Ap = 1.f;
    for (int tt = 0; tt < CHUNK; tt++) {
        const int t = t0 + tt;
        const float  v3 = __half2float(Vb[(size_t)t * HIDD]);
        const float4 kv = *(const float4*)(kerB + (size_t)t * NHh * KSs);
        const float  vm = kv.x * v0 + kv.y * v1 + kv.z * v2 + kv.w * v3;
        const float  uu = uB[(size_t)t * NHh];
        const float  vg = vB[(size_t)t * NHh];
        ctx = ctx * uu + vm * vg;
        Ap *= uu;
        v0 = v1; v1 = v2; v2 = v3;
    }
    g_ctxend[(size_t)(bh * NCH + chunk) * VDd + d] = ctx;
    if (d == 0) g_A[bh * NCH + chunk] = Ap;
}

__global__ void scan_pass2()
{
    const int bh = blockIdx.x, d = threadIdx.x;
    float ctx = 0.f;
    for (int c = 0; c < NCH; c++) {
        g_ctxinit[(size_t)(bh * NCH + c) * VDd + d] = ctx;
        ctx = g_ctxend[(size_t)(bh * NCH + c) * VDd + d] + g_A[bh * NCH + c] * ctx;
    }
}

__global__ void scan_pass3()
{
    const int chunk = blockIdx.x, h = blockIdx.y, b = blockIdx.z;
    const int d = threadIdx.x;
    const int bh = b * NHh + h;
    const int t0 = chunk * CHUNK;
    const __half* Vb  = g_v16 + (size_t)(b * Tt) * HIDD + h * VDd + d;
    const float* kerB = g_ker + (size_t)(b * Tt) * NHh * KSs + h * KSs;
    const float* uB   = g_u   + (size_t)(b * Tt) * NHh + h;
    const float* vB   = g_vv  + (size_t)(b * Tt) * NHh + h;
    const size_t obase = (size_t)(b * Tt) * HIDD + h * VDd + d;
    float v0 = (t0 >= 3) ? __half2float(Vb[(size_t)(t0 - 3) * HIDD]) : 0.f;
    float v1 = (t0 >= 2) ? __half2float(Vb[(size_t)(t0 - 2) * HIDD]) : 0.f;
    float v2 = (t0 >= 1) ? __half2float(Vb[(size_t)(t0 - 1) * HIDD]) : 0.f;
    float ctx = g_ctxinit[(size_t)(bh * NCH + chunk) * VDd + d];
    for (int tt = 0; tt < CHUNK; tt++) {
        const int t = t0 + tt;
        const float  v3 = __half2float(Vb[(size_t)t * HIDD]);
        const float4 kv = *(const float4*)(kerB + (size_t)t * NHh * KSs);
        const float  vm = kv.x * v0 + kv.y * v1 + kv.z * v2 + kv.w * v3;
        const float  uu = uB[(size_t)t * NHh];
        const float  vg = vB[(size_t)t * NHh];
        ctx = ctx * uu + vm * vg;
        g_ah[obase + (size_t)t * HIDD] = __float2half_rn(ctx);
        v0 = v1; v1 = v2; v2 = v3;
    }
}

// ---------------- launch ----------------
extern "C" void kernel_launch(void* const* d_in, const int* in_sizes, int n_in,
                              void* d_out, int out_size)
{
    (void)in_sizes; (void)n_in; (void)out_size;
    const float* x      = (const float*)d_in[0];
    const float* W_q    = (const float*)d_in[1];
    const float* b_q    = (const float*)d_in[2];
    // d_in[3] = W_k, d_in[4] = b_k : dead in the reference
    const float* W_v    = (const float*)d_in[5];
    const float* b_v    = (const float*)d_in[6];
    const float* kg_w1  = (const float*)d_in[7];
    const float* kg_b1  = (const float*)d_in[8];
    const float* kg_w2  = (const float*)d_in[9];
    const float* kg_b2  = (const float*)d_in[10];
    const float* gate_w = (const float*)d_in[11];
    const float* gate_b = (const float*)d_in[12];
    const float* W_out  = (const float*)d_in[13];
    const float* b_out  = (const float*)d_in[14];
    float* out = (float*)d_out;

    cudaFuncSetAttribute(gemm_mma<0>, cudaFuncAttributeMaxDynamicSharedMemorySize, SMEM_TOT);
    cudaFuncSetAttribute(gemm_mma<1>, cudaFuncAttributeMaxDynamicSharedMemorySize, SMEM_TOT);

    // input conversions
    convert_x_kernel<<<(Mrows * HIDD / 4) / 256, 256>>>(x);
    transpose_split_kernel<<<dim3(HIDD / 32, HIDD / 32), dim3(32, 8)>>>(W_q,   OSEL_WQ,  HIDD);
    transpose_split_kernel<<<dim3(HIDD / 32, HIDD / 32), dim3(32, 8)>>>(W_v,   OSEL_WV,  HIDD);
    transpose_split_kernel<<<dim3(HIDD / 32, HIDD / 32), dim3(32, 8)>>>(W_out, OSEL_WO,  HIDD);
    transpose_split_kernel<<<dim3(REDd / 32, HIDD / 32), dim3(32, 8)>>>(kg_w1, OSEL_KG1, REDd);

    // Q = x @ W_q + b_q (fp32 scratch for gate kernel)
    gemm_mma<0><<<dim3(HIDD / 128, Mrows / 128), 256, SMEM_TOT>>>(
        ASEL_X, BSEL_WQ, CSEL_Q, nullptr, b_q, HIDD);
    // V = x @ W_v + b_v  (fp16 output)
    gemm_mma<0><<<dim3(HIDD / 128, Mrows / 128), 256, SMEM_TOT>>>(
        ASEL_X, BSEL_WV, CSEL_V, nullptr, b_v, HIDD);
    // h = silu(x @ kg_w1 + kg_b1)
    gemm_mma<1><<<dim3(REDd / 128, Mrows / 128), 256, SMEM_TOT>>>(
        ASEL_X, BSEL_KG1, CSEL_H, nullptr, kg_b1, REDd);
    // RoPE + gate
    gate_kernel<<<(Mrows * NHh) / 4, 128>>>(gate_w, gate_b);
    // conv kernels
    kernels_kernel<<<Mrows / 16, 256>>>(kg_w2, kg_b2);
    // chunked linear scan (pass3 writes fp16 attn directly)
    scan_pass1<<<dim3(NCH, NHh, Bq), VDd>>>();
    scan_pass2<<<Bq * NHh, VDd>>>();
    scan_pass3<<<dim3(NCH, NHh, Bq), VDd>>>();
    // out = attn @ W_out + b_out
    gemm_mma<0><<<dim3(HIDD / 128, Mrows / 128), 256, SMEM_TOT>>>(
        ASEL_ATTN, BSEL_WO, CSEL_EXT, out, b_out, HIDD);
}

// round 15
// speedup vs baseline: 1.0844x; 1.0219x over previous
#include <cuda_runtime.h>
#include <cuda_fp16.h>
#include <stdint.h>
#include <string.h>
#include <math.h>

// ---------------- problem constants ----------------
#define Bq   4
#define Tt   4096
#define HIDD 1024
#define NHh  16
#define QKd  64
#define VDd  64
#define KSs  4
#define REDd 128
#define Mrows (Bq*Tt)          // 16384
#define CHUNK 64
#define NCH   (Tt/CHUNK)       // 64
#define KCH   32               // K chunks of 32 (K = 1024 for all GEMMs)

// ---------------- device scratch ----------------
__device__ __half g_xh[(size_t)Mrows*HIDD];
__device__ __half g_ah[(size_t)Mrows*HIDD];
__device__ __half g_wqt[HIDD*HIDD];
__device__ __half g_wvt[HIDD*HIDD];
__device__ __half g_wot[HIDD*HIDD];
__device__ __half g_kg1t[REDd*HIDD];
__device__ __half g_v16[(size_t)Mrows*HIDD];    // V in fp16 (scan input)
__device__ float g_Qf  [(size_t)Mrows*HIDD];    // Q fp32 (gate input)
__device__ float g_ker [(size_t)Mrows*NHh*KSs];
__device__ float g_u   [(size_t)Mrows*NHh];
__device__ float g_vv  [(size_t)Mrows*NHh];
__device__ float g_A      [Bq*NHh*NCH];
__device__ float g_ctxend [Bq*NHh*NCH*VDd];
__device__ float g_ctxinit[Bq*NHh*NCH*VDd];

// selectors
#define ASEL_X    0
#define ASEL_ATTN 1
#define BSEL_WQ   0
#define BSEL_WV   1
#define BSEL_KG1  2
#define BSEL_WO   3
#define CSEL_V    0
#define CSEL_Q    1
#define CSEL_EXT  2
#define CSEL_KER  3

// ---------------- PTX helpers (sm_100-baseline safe) ----------------
__device__ __forceinline__ uint32_t smem_u32(const void* p) {
    uint32_t a;
    asm("{ .reg .u64 t; cvta.to.shared.u64 t, %1; cvt.u32.u64 %0, t; }" : "=r"(a) : "l"(p));
    return a;
}
#define CP16(dst, src) \
    asm volatile("cp.async.cg.shared.global [%0], [%1], 16;" :: "r"(dst), "l"(src))
#define CP_COMMIT() asm volatile("cp.async.commit_group;" ::: "memory")

__device__ __forceinline__ void ldsm4(uint32_t* r, uint32_t addr) {
    asm volatile("ldmatrix.sync.aligned.m8n8.x4.shared.b16 {%0,%1,%2,%3},[%4];"
        : "=r"(r[0]), "=r"(r[1]), "=r"(r[2]), "=r"(r[3]) : "r"(addr));
}
__device__ __forceinline__ void ldsm2(uint32_t* r, uint32_t addr) {
    asm volatile("ldmatrix.sync.aligned.m8n8.x2.shared.b16 {%0,%1},[%2];"
        : "=r"(r[0]), "=r"(r[1]) : "r"(addr));
}
__device__ __forceinline__ void mma16816(float* c, const uint32_t* a, const uint32_t* b) {
    asm volatile("mma.sync.aligned.m16n8k16.row.col.f32.f16.f16.f32 "
        "{%0,%1,%2,%3},{%4,%5,%6,%7},{%8,%9},{%0,%1,%2,%3};"
        : "+f"(c[0]), "+f"(c[1]), "+f"(c[2]), "+f"(c[3])
        : "r"(a[0]), "r"(a[1]), "r"(a[2]), "r"(a[3]), "r"(b[0]), "r"(b[1]));
}

// smem: 4 stages; per stage 2 matrices (A, B), each 128 rows x 80B (32 fp16 + pad)
#define ROW_B     80
#define MAT_BYTES (128*ROW_B)          // 10240
#define STG_BYTES (2*MAT_BYTES)        // 20480
#define SMEM_TOT  (4*STG_BYTES)        // 81920
// ACT=3 tail layout (reuses stages): hS fp16 [128][136] = 34816 B, w2s fp32 [128][64] = 32768 B
#define HS_STRIDE 136
#define W2S_OFF   (128*HS_STRIDE*2)

__device__ __forceinline__ void load_stage(
    uint32_t sb, int st, int kc, int rowBase, int colBase,
    const __half* Aa, const __half* Bb, int tid)
{
    const uint32_t base = sb + st * STG_BYTES;
    const char* mats[2] = {
        (const char*)(Aa + (size_t)rowBase * HIDD),
        (const char*)(Bb + (size_t)colBase * HIDD) };
    #pragma unroll
    for (int i = 0; i < 4; i++) {
        const int idx = i * 256 + tid;            // 1024 16B chunks
        const int m   = idx >> 9;
        const int row = (idx >> 2) & 127;
        const int ch  = idx & 3;
        CP16(base + m * MAT_BYTES + row * ROW_B + ch * 16,
             mats[m] + (size_t)row * (HIDD * 2) + kc * 64 + ch * 16);
    }
}

// ---------------- GEMM: C[M,N] = A @ B^T + bias --------------------------------
// B stored [N,K]. ACT: 0 = bias; 3 = silu + fused ker GEMM (writes g_ker)
template<int ACT>
__global__ __launch_bounds__(256, 1) void gemm_mma(
    int a_sel, int b_sel, int c_sel, float* __restrict__ C_ext,
    const float* __restrict__ bias, int ldC,
    const float* __restrict__ w2, const float* __restrict__ b2)
{
    extern __shared__ char smem[];
    const uint32_t sb = smem_u32(smem);
    const int tid = threadIdx.x, wid = tid >> 5, lane = tid & 31;
    const int wm = wid >> 2, wn = wid & 3;        // 2 x 4 warp grid; warp tile 64 x 32
    const int rowBase = blockIdx.y * 128;
    const int colBase = blockIdx.x * 128;

    const __half *Aa, *Bb;
    Aa = (a_sel == ASEL_X) ? g_xh : g_ah;
    if (b_sel == BSEL_WQ)       Bb = g_wqt;
    else if (b_sel == BSEL_WV)  Bb = g_wvt;
    else if (b_sel == BSEL_KG1) Bb = g_kg1t;
    else                        Bb = g_wot;
    float* C = (c_sel == CSEL_Q) ? g_Qf : C_ext;

    float acc[4][4][4];
    #pragma unroll
    for (int i = 0; i < 4; i++)
        #pragma unroll
        for (int j = 0; j < 4; j++)
            #pragma unroll
            for (int k = 0; k < 4; k++) acc[i][j][k] = 0.f;

    // prologue: 3 stages in flight
    load_stage(sb, 0, 0, rowBase, colBase, Aa, Bb, tid); CP_COMMIT();
    load_stage(sb, 1, 1, rowBase, colBase, Aa, Bb, tid); CP_COMMIT();
    load_stage(sb, 2, 2, rowBase, colBase, Aa, Bb, tid); CP_COMMIT();

    const int g  = lane >> 3;       // ldmatrix x4 group
    const int lr = lane & 7;

    for (int kc = 0; kc < KCH; kc++) {
        asm volatile("cp.async.wait_group 2;" ::: "memory");
        __syncthreads();
        if (kc + 3 < KCH)
            load_stage(sb, (kc + 3) & 3, kc + 3, rowBase, colBase, Aa, Bb, tid);
        CP_COMMIT();   // uniform commit keeps wait_group arithmetic exact

        const uint32_t stb = sb + (kc & 3) * STG_BYTES;
        #pragma unroll
        for (int s = 0; s < 2; s++) {
            uint32_t ah[4][4], bh[4][2];
            #pragma unroll
            for (int i = 0; i < 4; i++) {
                const uint32_t arow = (uint32_t)(wm * 64 + i * 16 + (g & 1) * 8 + lr);
                const uint32_t acol = (uint32_t)(s * 32 + (g >> 1) * 16);
                ldsm4(ah[i], stb + arow * ROW_B + acol);
            }
            #pragma unroll
            for (int j = 0; j < 4; j++) {
                const uint32_t brow = (uint32_t)(wn * 32 + j * 8 + lr);
                const uint32_t bcol = (uint32_t)(s * 32 + (g & 1) * 16);
                ldsm2(bh[j], stb + MAT_BYTES + brow * ROW_B + bcol);
            }
            #pragma unroll
            for (int i = 0; i < 4; i++)
                #pragma unroll
                for (int j = 0; j < 4; j++)
                    mma16816(acc[i][j], ah[i], bh[j]);
        }
    }

    const int q = lane >> 2, r4 = lane & 3;

    if (ACT == 3) {
        // fused: hS = silu(h); ker = hS @ w2 + b2. Grid is (1,128) -> under-occupied,
        // so this in-tile tail is nearly free vs a separate kernel + g_h round trip.
        __half* hS  = (__half*)smem;                 // [128][HS_STRIDE]
        float*  w2s = (float*)(smem + W2S_OFF);      // [128][64]
        __syncthreads();                             // mainloop smem reads done
        #pragma unroll
        for (int i = 0; i < 4; i++) {
            const int r0 = wm * 64 + i * 16 + q;
            #pragma unroll
            for (int j = 0; j < 4; j++) {
                const int col = wn * 32 + j * 8 + r4 * 2;
                const float b0 = bias[col], b1 = bias[col + 1];
                float v0 = acc[i][j][0] + b0, v1 = acc[i][j][1] + b1;
                float v2 = acc[i][j][2] + b0, v3 = acc[i][j][3] + b1;
                v0 = v0 / (1.f + expf(-v0));
                v1 = v1 / (1.f + expf(-v1));
                v2 = v2 / (1.f + expf(-v2));
                v3 = v3 / (1.f + expf(-v3));
                hS[r0 * HS_STRIDE + col]           = __float2half_rn(v0);
                hS[r0 * HS_STRIDE + col + 1]       = __float2half_rn(v1);
                hS[(r0 + 8) * HS_STRIDE + col]     = __float2half_rn(v2);
                hS[(r0 + 8) * HS_STRIDE + col + 1] = __float2half_rn(v3);
            }
        }
        for (int i = tid; i < REDd * 64; i += 256) w2s[i] = w2[i];
        __syncthreads();
        const float bb0 = b2[lane], bb1 = b2[lane + 32];
        for (int rr = 0; rr < 16; rr++) {
            const int row = wid * 16 + rr;
            float a0 = bb0, a1 = bb1;
            #pragma unroll 8
            for (int k = 0; k < REDd; k++) {
                const float hv = __half2float(hS[row * HS_STRIDE + k]);
                a0 += hv * w2s[k * 64 + lane];
                a1 += hv * w2s[k * 64 + lane + 32];
            }
            g_ker[(size_t)(rowBase + row) * 64 + lane]      = a0;
            g_ker[(size_t)(rowBase + row) * 64 + lane + 32] = a1;
        }
        return;
    }

    // epilogue: bias; V goes to fp16, others fp32
    #pragma unroll
    for (int i = 0; i < 4; i++) {
        const int row0 = rowBase + wm * 64 + i * 16 + q;
        #pragma unroll
        for (int j = 0; j < 4; j++) {
            const int col = colBase + wn * 32 + j * 8 + r4 * 2;
            const float b0 = bias[col], b1 = bias[col + 1];
            const float v0 = acc[i][j][0] + b0, v1 = acc[i][j][1] + b1;
            const float v2 = acc[i][j][2] + b0, v3 = acc[i][j][3] + b1;
            if (c_sel == CSEL_V) {
                *(__half2*)(g_v16 + (size_t)row0 * ldC + col)       = __floats2half2_rn(v0, v1);
                *(__half2*)(g_v16 + (size_t)(row0 + 8) * ldC + col) = __floats2half2_rn(v2, v3);
            } else {
                *(float2*)(C + (size_t)row0 * ldC + col)       = make_float2(v0, v1);
                *(float2*)(C + (size_t)(row0 + 8) * ldC + col) = make_float2(v2, v3);
            }
        }
    }
}

// ---------------- x -> fp16 (single plane) ----------------
__global__ void convert_x_kernel(const float* __restrict__ x)
{
    const size_t i = (size_t)blockIdx.x * blockDim.x + threadIdx.x;  // float4 index
    const float4 v = ((const float4*)x)[i];
    __half2 lo = __floats2half2_rn(v.x, v.y);
    __half2 hi = __floats2half2_rn(v.z, v.w);
    uint2 H;
    memcpy(&H.x, &lo, 4);
    memcpy(&H.y, &hi, 4);
    ((uint2*)g_xh)[i] = H;
}

// ---------------- all W[K,N] -> Wt [N,K] fp16 (one launch) ----------------
__global__ void transpose_all_kernel(const float* __restrict__ W_q,
                                     const float* __restrict__ W_v,
                                     const float* __restrict__ W_out,
                                     const float* __restrict__ kg_w1)
{
    const int z = blockIdx.z;
    const float* W;
    __half* dst;
    int N;
    if (z == 0)      { W = W_q;   dst = g_wqt;  N = HIDD; }
    else if (z == 1) { W = W_v;   dst = g_wvt;  N = HIDD; }
    else if (z == 2) { W = W_out; dst = g_wot;  N = HIDD; }
    else             { W = kg_w1; dst = g_kg1t; N = REDd;
                       if (blockIdx.x >= REDd / 32) return; }

    __shared__ float tile[32][33];
    const int n0 = blockIdx.x * 32, k0 = blockIdx.y * 32;
    const int tx = threadIdx.x, ty = threadIdx.y;   // 32 x 8
    #pragma unroll
    for (int j = 0; j < 32; j += 8)
        tile[ty + j][tx] = W[(size_t)(k0 + ty + j) * N + n0 + tx];
    __syncthreads();
    #pragma unroll
    for (int j = 0; j < 32; j += 8) {
        const int n = n0 + ty + j, k = k0 + tx;
        dst[(size_t)n * HIDD + k] = __float2half_rn(tile[tx][ty + j]);
    }
}

// ---------------- fused RoPE + gate (reads g_Qf) ----------
__global__ void gate_kernel(const float* __restrict__ gate_w,
                            const float* __restrict__ gate_b)
{
    const int gw   = (blockIdx.x * blockDim.x + threadIdx.x) >> 5;
    const int lane = threadIdx.x & 31;
    const int h    = gw % NHh;
    const int bt   = gw / NHh;
    const int t    = bt % Tt;

    const float* qp = g_Qf + (size_t)bt * HIDD + h * QKd;
    const float q1 = qp[lane];
    const float q2 = qp[lane + 32];

    const float freq = powf(10000.0f, -(float)lane / 16.0f);
    float s, c;
    sincosf((float)t * freq, &s, &c);
    const float r1 = q1 * c - q2 * s;
    const float r2 = q1 * s + q2 * c;

    float du = r1 * gate_w[lane * 2]     + r2 * gate_w[(lane + 32) * 2];
    float dv = r1 * gate_w[lane * 2 + 1] + r2 * gate_w[(lane + 32) * 2 + 1];
    #pragma unroll
    for (int o = 16; o > 0; o >>= 1) {
        du += __shfl_down_sync(0xffffffffu, du, o);
        dv += __shfl_down_sync(0xffffffffu, dv, o);
    }
    if (lane == 0) {
        g_u [gw] = 1.f / (1.f + expf(-(du + gate_b[0])));
        g_vv[gw] = 1.f / (1.f + expf(-(dv + gate_b[1])));
    }
}

// ---------------- chunked scan (fused 4-tap Vmix, fp16 V, CHUNK=64) ------------
__global__ void scan_pass1()
{
    const int chunk = blockIdx.x, h = blockIdx.y, b = blockIdx.z;
    const int d = threadIdx.x;
    const int bh = b * NHh + h;
    const int t0 = chunk * CHUNK;
    const __half* Vb  = g_v16 + (size_t)(b * Tt) * HIDD + h * VDd + d;
    const float* kerB = g_ker + (size_t)(b * Tt) * NHh * KSs + h * KSs;
    const float* uB   = g_u   + (size_t)(b * Tt) * NHh + h;
    const float* vB   = g_vv  + (size_t)(b * Tt) * NHh + h;
    float v0 = (t0 >= 3) ? __half2float(Vb[(size_t)(t0 - 3) * HIDD]) : 0.f;
    float v1 = (t0 >= 2) ? __half2float(Vb[(size_t)(t0 - 2) * HIDD]) : 0.f;
    float v2 = (t0 >= 1) ? __half2float(Vb[(size_t)(t0 - 1) * HIDD]) : 0.f;
    float ctx = 0.f, Ap = 1.f;
    for (int tt = 0; tt < CHUNK; tt++) {
        const int t = t0 + tt;
        const float  v3 = __half2float(Vb[(size_t)t * HIDD]);
        const float4 kv = *(const float4*)(kerB + (size_t)t * NHh * KSs);
        const float  vm = kv.x * v0 + kv.y * v1 + kv.z * v2 + kv.w * v3;
        const float  uu = uB[(size_t)t * NHh];
        const float  vg = vB[(size_t)t * NHh];
        ctx = ctx * uu + vm * vg;
        Ap *= uu;
        v0 = v1; v1 = v2; v2 = v3;
    }
    g_ctxend[(size_t)(bh * NCH + chunk) * VDd + d] = ctx;
    if (d == 0) g_A[bh * NCH + chunk] = Ap;
}

__global__ void scan_pass2()
{
    const int bh = blockIdx.x, d = threadIdx.x;
    float ctx = 0.f;
    for (int c = 0; c < NCH; c++) {
        g_ctxinit[(size_t)(bh * NCH + c) * VDd + d] = ctx;
        ctx = g_ctxend[(size_t)(bh * NCH + c) * VDd + d] + g_A[bh * NCH + c] * ctx;
    }
}

__global__ void scan_pass3()
{
    const int chunk = blockIdx.x, h = blockIdx.y, b = blockIdx.z;
    const int d = threadIdx.x;
    const int bh = b * NHh + h;
    const int t0 = chunk * CHUNK;
    const __half* Vb  = g_v16 + (size_t)(b * Tt) * HIDD + h * VDd + d;
    const float* kerB = g_ker + (size_t)(b * Tt) * NHh * KSs + h * KSs;
    const float* uB   = g_u   + (size_t)(b * Tt) * NHh + h;
    const float* vB   = g_vv  + (size_t)(b * Tt) * NHh + h;
    const size_t obase = (size_t)(b * Tt) * HIDD + h * VDd + d;
    float v0 = (t0 >= 3) ? __half2float(Vb[(size_t)(t0 - 3) * HIDD]) : 0.f;
    float v1 = (t0 >= 2) ? __half2float(Vb[(size_t)(t0 - 2) * HIDD]) : 0.f;
    float v2 = (t0 >= 1) ? __half2float(Vb[(size_t)(t0 - 1) * HIDD]) : 0.f;
    float ctx = g_ctxinit[(size_t)(bh * NCH + chunk) * VDd + d];
    for (int tt = 0; tt < CHUNK; tt++) {
        const int t = t0 + tt;
        const float  v3 = __half2float(Vb[(size_t)t * HIDD]);
        const float4 kv = *(const float4*)(kerB + (size_t)t * NHh * KSs);
        const float  vm = kv.x * v0 + kv.y * v1 + kv.z * v2 + kv.w * v3;
        const float  uu = uB[(size_t)t * NHh];
        const float  vg = vB[(size_t)t * NHh];
        ctx = ctx * uu + vm * vg;
        g_ah[obase + (size_t)t * HIDD] = __float2half_rn(ctx);
        v0 = v1; v1 = v2; v2 = v3;
    }
}

// ---------------- launch ----------------
extern "C" void kernel_launch(void* const* d_in, const int* in_sizes, int n_in,
                              void* d_out, int out_size)
{
    (void)in_sizes; (void)n_in; (void)out_size;
    const float* x      = (const float*)d_in[0];
    const float* W_q    = (const float*)d_in[1];
    const float* b_q    = (const float*)d_in[2];
    // d_in[3] = W_k, d_in[4] = b_k : dead in the reference
    const float* W_v    = (const float*)d_in[5];
    const float* b_v    = (const float*)d_in[6];
    const float* kg_w1  = (const float*)d_in[7];
    const float* kg_b1  = (const float*)d_in[8];
    const float* kg_w2  = (const float*)d_in[9];
    const float* kg_b2  = (const float*)d_in[10];
    const float* gate_w = (const float*)d_in[11];
    const float* gate_b = (const float*)d_in[12];
    const float* W_out  = (const float*)d_in[13];
    const float* b_out  = (const float*)d_in[14];
    float* out = (float*)d_out;

    cudaFuncSetAttribute(gemm_mma<0>, cudaFuncAttributeMaxDynamicSharedMemorySize, SMEM_TOT);
    cudaFuncSetAttribute(gemm_mma<3>, cudaFuncAttributeMaxDynamicSharedMemorySize, SMEM_TOT);

    // input conversions (transposes merged into one launch)
    convert_x_kernel<<<(Mrows * HIDD / 4) / 256, 256>>>(x);
    transpose_all_kernel<<<dim3(HIDD / 32, HIDD / 32, 4), dim3(32, 8)>>>(W_q, W_v, W_out, kg_w1);

    // Q = x @ W_q + b_q (fp32 scratch for gate kernel)
    gemm_mma<0><<<dim3(HIDD / 128, Mrows / 128), 256, SMEM_TOT>>>(
        ASEL_X, BSEL_WQ, CSEL_Q, nullptr, b_q, HIDD, nullptr, nullptr);
    // V = x @ W_v + b_v  (fp16 output)
    gemm_mma<0><<<dim3(HIDD / 128, Mrows / 128), 256, SMEM_TOT>>>(
        ASEL_X, BSEL_WV, CSEL_V, nullptr, b_v, HIDD, nullptr, nullptr);
    // h = silu(x @ kg_w1 + kg_b1); ker = h @ kg_w2 + kg_b2 (fused, writes g_ker)
    gemm_mma<3><<<dim3(REDd / 128, Mrows / 128), 256, SMEM_TOT>>>(
        ASEL_X, BSEL_KG1, CSEL_KER, nullptr, kg_b1, REDd, kg_w2, kg_b2);
    // RoPE + gate
    gate_kernel<<<(Mrows * NHh) / 4, 128>>>(gate_w, gate_b);
    // chunked linear scan (pass3 writes fp16 attn directly)
    scan_pass1<<<dim3(NCH, NHh, Bq), VDd>>>();
    scan_pass2<<<Bq * NHh, VDd>>>();
    scan_pass3<<<dim3(NCH, NHh, Bq), VDd>>>();
    // out = attn @ W_out + b_out
    gemm_mma<0><<<dim3(HIDD / 128, Mrows / 128), 256, SMEM_TOT>>>(
        ASEL_ATTN, BSEL_WO, CSEL_EXT, out, b_out, HIDD, nullptr, nullptr);
}